// round 16
// baseline (speedup 1.0000x reference)
#include <cuda_runtime.h>
#include <cuda_fp16.h>
#include <math.h>
#include <stdint.h>

// ---------------- problem constants ----------------
#define TN 4096
#define HD 2048
#define ID 4096
#define NE 8
#define NK 2
#define BM 128
#define BN 128
#define BK 64
#define MAXSLOT (TN*NK + NE*BM)   // 9216
#define MAXMT   (MAXSLOT/BM)      // 72
#define STAGE 32768               // A 16K | B 16K
#define G_SMEM (3*STAGE)          // 96 KB -> 2 CTAs/SM
// phase-2 prep queue: gate chunk1 [0,4096) | up chunk1 [4096,8192) | wd [8192,16384)
#define Q1 8192
#define QTOTAL 16384
#define PREP_SMEM (64*129*4)      // 33024 B

// ---------------- device scratch ----------------
static __device__ __align__(16) __half g_x1 [(size_t)MAXSLOT*HD];      // x fp16
static __device__ __align__(16) __half g_w1 [(size_t)NE*2*ID*HD];      // fine-interleaved gate/up B' fp16
static __device__ __align__(16) __half g_wd [(size_t)NE*HD*ID];        // down W^T fp16
static __device__ __align__(16) __half g_a1 [(size_t)MAXSLOT*ID];      // act fp16
static __device__ int   g_cnt[NE];
static __device__ int   g_cnt2[NE];
static __device__ int   g_off[NE];
static __device__ int   g_tok_e[TN*NK];
static __device__ float g_tok_w[TN*NK];
static __device__ int   g_tok_slot[TN*NK];
static __device__ int   g_slot_token[MAXSLOT];
static __device__ float g_slot_w[MAXSLOT];
static __device__ int   g_tile_e[MAXMT];
static __device__ unsigned int g_done[MAXMT];   // per-mtile GEMM1 completion counters
static __device__ unsigned int g_take;          // prep queue take counter
static __device__ unsigned int g_done1;         // gate/up chunk1 done (target Q1)
static __device__ unsigned int g_done2;         // wd done (target QTOTAL-Q1)

// ---------------- helpers ----------------
__device__ __forceinline__ uint32_t smem_u32(const void* p) {
    uint32_t a;
    asm("{ .reg .u64 t; cvta.to.shared.u64 t, %1; cvt.u32.u64 %0, t; }" : "=r"(a) : "l"(p));
    return a;
}
__device__ __forceinline__ void cp16(uint32_t dst, const void* src) {
    asm volatile("cp.async.cg.shared.global [%0], [%1], 16;" :: "r"(dst), "l"(src));
}
#define CP_COMMIT() asm volatile("cp.async.commit_group;" ::: "memory")
#define CP_WAIT1()  asm volatile("cp.async.wait_group 1;" ::: "memory")
__device__ __forceinline__ void ldsm4(uint32_t* r, uint32_t addr) {
    asm volatile("ldmatrix.sync.aligned.m8n8.x4.shared.b16 {%0,%1,%2,%3}, [%4];"
        : "=r"(r[0]), "=r"(r[1]), "=r"(r[2]), "=r"(r[3]) : "r"(addr));
}
__device__ __forceinline__ void mmah(float* d, const uint32_t* a, uint32_t b0, uint32_t b1) {
    asm volatile("mma.sync.aligned.m16n8k16.row.col.f32.f16.f16.f32 "
        "{%0,%1,%2,%3}, {%4,%5,%6,%7}, {%8,%9}, {%0,%1,%2,%3};"
        : "+f"(d[0]), "+f"(d[1]), "+f"(d[2]), "+f"(d[3])
        : "r"(a[0]), "r"(a[1]), "r"(a[2]), "r"(a[3]), "r"(b0), "r"(b1));
}
__device__ __forceinline__ void redv2(float* gptr, float a, float b) {
    asm volatile("red.global.add.v2.f32 [%0], {%1, %2};"
        :: "l"(gptr), "f"(a), "f"(b) : "memory");
}
__device__ __forceinline__ unsigned ld_acq(const unsigned* p) {
    unsigned v;
    asm volatile("ld.acquire.gpu.global.u32 %0, [%1];" : "=r"(v) : "l"(p) : "memory");
    return v;
}
__device__ __forceinline__ void red_rel_inc(unsigned* p) {
    asm volatile("red.release.gpu.global.add.u32 [%0], 1;" :: "l"(p) : "memory");
}
__device__ __forceinline__ float gelu_tanh(float v) {
    float w = 0.7978845608028654f * v * (1.0f + 0.044715f * v * v);
    float t;
    asm("tanh.approx.f32 %0, %1;" : "=f"(t) : "f"(w));
    return 0.5f * v * (1.0f + t);
}
__device__ __forceinline__ uint32_t packh2(float a, float b) {
    __half ha = __float2half_rn(a), hb = __float2half_rn(b);
    return (uint32_t)__half_as_ushort(ha) | ((uint32_t)__half_as_ushort(hb) << 16);
}

// ---------------- prep tile body (shared by chunk0 kernel, p2 kernel, stealers) ----------------
__device__ void prep_body(const float* __restrict__ src, __half* __restrict__ dst,
                          int K, int N, int nrows, int mode, int n0, int k0, int e,
                          float* s /* 64*129 floats */) {
    const float* sp = src + (size_t)e * K * N + (size_t)k0 * N + n0;
#pragma unroll
    for (int i = 0; i < 8; i++) {
        int q = threadIdx.x + i * 256;
        int kr = q >> 5, c4 = (q & 31) * 4;
        float4 v = *(const float4*)(sp + (size_t)kr * N + c4);
        float* d = s + kr * 129 + c4;
        d[0] = v.x; d[1] = v.y; d[2] = v.z; d[3] = v.w;
    }
    __syncthreads();
    __half* dp = dst + (size_t)e * nrows * K + k0;
#pragma unroll
    for (int i = 0; i < 4; i++) {
        int j = threadIdx.x + i * 256;
        int n = j >> 3, kq = (j & 7) * 8;
        uint32_t w[4];
#pragma unroll
        for (int t = 0; t < 4; t++)
            w[t] = packh2(s[(kq + 2*t) * 129 + n], s[(kq + 2*t + 1) * 129 + n]);
        int ng = n0 + n;
        size_t row;
        if (mode == 0)      row = (size_t)ng;
        else if (mode == 1) row = (size_t)(ng >> 3) * 16 + (ng & 7);
        else                row = (size_t)(ng >> 3) * 16 + (ng & 7) + 8;
        *(uint4*)(dp + row * K + kq) = *(uint4*)w;
    }
}

// execute one queue tile
__device__ void do_qtile(unsigned t, const float* wg, const float* wu, const float* wd,
                         float* s) {
    if (t < 4096u) {               // gate chunk1
        int x = t & 15, kb = (t >> 4) & 31, e = t >> 9;
        prep_body(wg, g_w1, HD, ID, 2*ID, 1, (x + 16) * 128, kb * 64, e, s);
    } else if (t < 8192u) {        // up chunk1
        unsigned u = t - 4096u;
        int x = u & 15, kb = (u >> 4) & 31, e = u >> 9;
        prep_body(wu, g_w1, HD, ID, 2*ID, 2, (x + 16) * 128, kb * 64, e, s);
    } else {                       // wd
        unsigned u = t - 8192u;
        int x = u & 15, kb = (u >> 4) & 63, e = u >> 10;
        prep_body(wd, g_wd, ID, HD, HD, 0, x * 128, kb * 64, e, s);
    }
}

// steal from the queue until empty (CTA-cooperative). Never blocks.
__device__ void steal_all(const float* wg, const float* wu, const float* wd, float* s) {
    __shared__ unsigned s_t;
    for (;;) {
        __syncthreads();
        if (threadIdx.x == 0) s_t = atomicAdd(&g_take, 1u);
        __syncthreads();
        unsigned t = s_t;
        if (t >= QTOTAL) break;
        do_qtile(t, wg, wu, wd, s);
        __syncthreads();
        if (threadIdx.x == 0) red_rel_inc(t < Q1 ? &g_done1 : &g_done2);
    }
    __syncthreads();
}

// ---------------- routing ----------------
__global__ void k_zero() {
    int i = threadIdx.x;
    if (i < NE) { g_cnt[i] = 0; g_cnt2[i] = 0; }
    if (i < MAXMT) g_done[i] = 0;
    if (i == 0) { g_take = 0; g_done1 = 0; g_done2 = 0; }
}

__global__ void k_router(const float* __restrict__ x, const float* __restrict__ gw,
                         float* __restrict__ out_logits, float* __restrict__ out_final) {
    const int t = blockIdx.x;
    const int tid = threadIdx.x;
    // zero this token's output row (GEMM2 accumulates into it)
    {
        float4 z = make_float4(0.f, 0.f, 0.f, 0.f);
        float4* orow = (float4*)(out_final + (size_t)t * HD);
#pragma unroll
        for (int i = 0; i < 2; i++) orow[tid + i * 256] = z;
    }
    float acc[NE];
#pragma unroll
    for (int e = 0; e < NE; e++) acc[e] = 0.f;
    const float* xr = x + (size_t)t * HD;
    for (int h = tid; h < HD; h += 256) {
        float xv = xr[h];
        const float* g = gw + (size_t)h * NE;
#pragma unroll
        for (int e = 0; e < NE; e++) acc[e] += xv * g[e];
    }
    __shared__ float red[256][NE];
#pragma unroll
    for (int e = 0; e < NE; e++) red[tid][e] = acc[e];
    __syncthreads();
    for (int off = 128; off > 0; off >>= 1) {
        if (tid < off) {
#pragma unroll
            for (int e = 0; e < NE; e++) red[tid][e] += red[tid + off][e];
        }
        __syncthreads();
    }
    if (tid == 0) {
        float l[NE];
#pragma unroll
        for (int e = 0; e < NE; e++) l[e] = red[0][e];
        if (out_logits) {
#pragma unroll
            for (int e = 0; e < NE; e++) out_logits[(size_t)t * NE + e] = l[e];
        }
        int e0 = 0;
#pragma unroll
        for (int e = 1; e < NE; e++) if (l[e] > l[e0]) e0 = e;
        int e1 = -1; float l1 = -1e30f;
#pragma unroll
        for (int e = 0; e < NE; e++) if (e != e0 && l[e] > l1) { l1 = l[e]; e1 = e; }
        float d = expf(l1 - l[e0]);
        float w0 = 1.f / (1.f + d);
        g_tok_e[2*t] = e0; g_tok_e[2*t+1] = e1;
        g_tok_w[2*t] = w0; g_tok_w[2*t+1] = 1.f - w0;
        atomicAdd(&g_cnt[e0], 1);
        atomicAdd(&g_cnt[e1], 1);
    }
}

__global__ void k_offsets() {
    const int tid = threadIdx.x;
    if (tid == 0) {
        int cur = 0, mt = 0;
        for (int e = 0; e < NE; e++) {
            g_off[e] = cur;
            int tiles = (g_cnt[e] + BM - 1) / BM;
            for (int j = 0; j < tiles; j++) g_tile_e[mt++] = e;
            cur += tiles * BM;
        }
        for (; mt < MAXMT; mt++) g_tile_e[mt] = -1;
    }
    for (int i = tid; i < MAXSLOT; i += blockDim.x) g_slot_token[i] = -1;
}

__global__ void k_scatter() {
    int t = blockIdx.x * blockDim.x + threadIdx.x;
    if (t >= TN) return;
#pragma unroll
    for (int k = 0; k < NK; k++) {
        int e = g_tok_e[2*t + k];
        int pos = atomicAdd(&g_cnt2[e], 1);
        int slot = g_off[e] + pos;
        g_slot_token[slot] = t;
        g_slot_w[slot] = g_tok_w[2*t + k];
        g_tok_slot[2*t + k] = slot;
    }
}

// ---------------- prep chunk0 (grid-based): gate/up n in [0,2048) ----------------
__global__ void k_prep0(const float* __restrict__ src, __half* __restrict__ dst, int mode) {
    extern __shared__ float sP[];
    prep_body(src, dst, HD, ID, 2*ID, mode, blockIdx.x * 128, blockIdx.y * 64, blockIdx.z, sP);
}

// ---------------- p2: queue-draining prep kernel (chunk1 gate/up + wd) ----------------
__global__ void k_prep2(const float* __restrict__ wg, const float* __restrict__ wu,
                        const float* __restrict__ wd) {
    extern __shared__ float sP[];
    steal_all(wg, wu, wd, sP);
}

// ---------------- prep: gather x rows per slot -> fp16 ----------------
__global__ void k_gatherx(const float* __restrict__ x) {
    int slot = blockIdx.x;
    int t = g_slot_token[slot];
    __half* row = g_x1 + (size_t)slot * HD;
    for (int k = threadIdx.x * 2; k < HD; k += 512) {
        float v0 = 0.f, v1 = 0.f;
        if (t >= 0) {
            v0 = x[(size_t)t * HD + k];
            v1 = x[(size_t)t * HD + k + 1];
        }
        *(uint32_t*)&row[k] = packh2(v0, v1);
    }
}

// ---------------- FUSED GEMM1+GEMM2 (one launch) ----------------
// grid (MAXMT, 80): y in [0,64)  -> GEMM1 (yb>=32 first steals/waits chunk1 prep)
//                   y in [64,80) -> GEMM2 (steals/waits wd prep, then waits g_done[mt])
// Every wait is preceded by queue-stealing => guaranteed progress, no deadlock.
__global__ void __launch_bounds__(256, 2)
k_gemm_fused(const __half* __restrict__ A1, const __half* __restrict__ B1,
             const __half* __restrict__ A2, const __half* __restrict__ B2,
             float* __restrict__ out,
             const float* __restrict__ wg, const float* __restrict__ wu,
             const float* __restrict__ wd) {
    const int mt = blockIdx.x;
    const int e = g_tile_e[mt];
    if (e < 0) return;                 // pad tile: both phases skip
    const int m0 = mt * BM;
    extern __shared__ char smraw[];
    const uint32_t sbase = smem_u32(smraw);
    const int tid = threadIdx.x, lane = tid & 31, wid = tid >> 5;
    const int wm = (wid >> 2) * 64, wn = (wid & 3) * 32;
    const int prow = tid >> 3, pkc = tid & 7;
    const uint32_t sw = ((uint32_t)(pkc ^ (prow & 7))) << 4;
    const int lrow = lane & 15, lk = lane >> 4;
    const int r0 = lane >> 2, c0 = (lane & 3) * 2;

    float acc[4][4][4];
#pragma unroll
    for (int i = 0; i < 4; i++)
#pragma unroll
        for (int j = 0; j < 4; j++)
#pragma unroll
            for (int q = 0; q < 4; q++) acc[i][j][q] = 0.f;

    if (blockIdx.y < 64) {
        // ================= GEMM1 =================
        const int yb = blockIdx.y;
        if (yb >= 32) {
            // chunk1 B' rows: steal remaining prep work, then wait (progress-safe)
            steal_all(wg, wu, wd, (float*)smraw);
            if (tid == 0) {
                while (ld_acq(&g_done1) < (unsigned)Q1) __nanosleep(128);
            }
            __syncthreads();
        }
        const int nb0 = yb * 128;
        const __half* aptr = A1 + (size_t)(m0 + prow) * HD + pkc * 8;
        const __half* bptr = B1 + ((size_t)e * (2 * ID) + nb0 + prow) * HD + pkc * 8;

        auto load_stage = [&](int s, int c) {
            uint32_t d = sbase + s * STAGE;
            const __half* a = aptr + c * BK;
            const __half* b = bptr + c * BK;
#pragma unroll
            for (int t = 0; t < 4; t++) {
                uint32_t dd = d + (prow + 32*t) * 128 + sw;
                cp16(dd,          a + (size_t)(32*t) * HD);
                cp16(dd + 16384,  b + (size_t)(32*t) * HD);
            }
        };
        load_stage(0, 0); CP_COMMIT();
        load_stage(1, 1); CP_COMMIT();

        const int Kc = HD / BK;   // 32
        for (int c = 0; c < Kc; c++) {
            CP_WAIT1();
            __syncthreads();
            if (c + 2 < Kc) load_stage((c + 2) % 3, c + 2);
            CP_COMMIT();
            const uint32_t sa = sbase + (c % 3) * STAGE;
#pragma unroll
            for (int ks = 0; ks < 4; ks++) {
                uint32_t ah[4][4], bf[2][4];
                const int kc = ks * 2 + lk;
#pragma unroll
                for (int mi = 0; mi < 4; mi++) {
                    int row = wm + mi * 16 + lrow;
                    ldsm4(ah[mi], sa + row * 128 + ((kc ^ (row & 7)) << 4));
                }
#pragma unroll
                for (int ng = 0; ng < 2; ng++) {
                    int row = wn + ng * 16 + lrow;
                    ldsm4(bf[ng], sa + 16384 + row * 128 + ((kc ^ (row & 7)) << 4));
                }
#pragma unroll
                for (int mi = 0; mi < 4; mi++)
#pragma unroll
                    for (int nf = 0; nf < 4; nf++) {
                        const int ng = nf >> 1, p = nf & 1;
                        mmah(acc[mi][nf], ah[mi], bf[ng][p], bf[ng][p + 2]);
                    }
            }
        }

        // epilogue: nf pairs (0,1)/(2,3) = gate/up for same output cols
        const int ob = yb * 64 + (wn >> 1);
#pragma unroll
        for (int mi = 0; mi < 4; mi++) {
            int row = m0 + wm + mi * 16 + r0;
#pragma unroll
            for (int g = 0; g < 2; g++) {
                const float* ag = acc[mi][2*g];
                const float* au = acc[mi][2*g + 1];
                int col = ob + g * 8 + c0;
                float a0 = gelu_tanh(ag[0]) * au[0];
                float a1 = gelu_tanh(ag[1]) * au[1];
                float a2 = gelu_tanh(ag[2]) * au[2];
                float a3 = gelu_tanh(ag[3]) * au[3];
                *(uint32_t*)(g_a1 + (size_t)row * ID + col) = packh2(a0, a1);
                *(uint32_t*)(g_a1 + (size_t)(row + 8) * ID + col) = packh2(a2, a3);
            }
        }
        __syncthreads();
        if (tid == 0) red_rel_inc(&g_done[mt]);
    } else {
        // ================= GEMM2 =================
        const int n0 = (blockIdx.y - 64) * BN;
        // wd prep: steal remaining work, then wait (progress-safe)
        steal_all(wg, wu, wd, (float*)smraw);
        if (tid == 0) {
            while (ld_acq(&g_done2) < (unsigned)(QTOTAL - Q1)) __nanosleep(128);
            while (ld_acq(&g_done[mt]) < 64u) __nanosleep(128);
        }
        __syncthreads();

        const __half* aptr = A2 + (size_t)(m0 + prow) * ID + pkc * 8;
        const __half* bptr = B2 + ((size_t)e * HD + n0 + prow) * ID + pkc * 8;

        auto load_stage = [&](int s, int c) {
            uint32_t d = sbase + s * STAGE;
            const __half* a = aptr + c * BK;
            const __half* b = bptr + c * BK;
#pragma unroll
            for (int t = 0; t < 4; t++) {
                uint32_t dd = d + (prow + 32*t) * 128 + sw;
                cp16(dd,          a + (size_t)(32*t) * ID);
                cp16(dd + 16384,  b + (size_t)(32*t) * ID);
            }
        };
        load_stage(0, 0); CP_COMMIT();
        load_stage(1, 1); CP_COMMIT();

        const int Kc = ID / BK;   // 64
        for (int c = 0; c < Kc; c++) {
            CP_WAIT1();
            __syncthreads();
            if (c + 2 < Kc) load_stage((c + 2) % 3, c + 2);
            CP_COMMIT();
            const uint32_t sa = sbase + (c % 3) * STAGE;
#pragma unroll
            for (int ks = 0; ks < 4; ks++) {
                uint32_t ah[4][4], bf[2][4];
                const int kc = ks * 2 + lk;
#pragma unroll
                for (int mi = 0; mi < 4; mi++) {
                    int row = wm + mi * 16 + lrow;
                    ldsm4(ah[mi], sa + row * 128 + ((kc ^ (row & 7)) << 4));
                }
#pragma unroll
                for (int ng = 0; ng < 2; ng++) {
                    int row = wn + ng * 16 + lrow;
                    ldsm4(bf[ng], sa + 16384 + row * 128 + ((kc ^ (row & 7)) << 4));
                }
#pragma unroll
                for (int mi = 0; mi < 4; mi++)
#pragma unroll
                    for (int nf = 0; nf < 4; nf++) {
                        const int ng = nf >> 1, p = nf & 1;
                        mmah(acc[mi][nf], ah[mi], bf[ng][p], bf[ng][p + 2]);
                    }
            }
        }

        // fused combine epilogue: out[token, col] += w_slot * acc  (red.v2)
#pragma unroll
        for (int mi = 0; mi < 4; mi++) {
            int rowA = m0 + wm + mi * 16 + r0;
            int rowB = rowA + 8;
            int tA = g_slot_token[rowA], tB = g_slot_token[rowB];
            float wA = g_slot_w[rowA],  wB = g_slot_w[rowB];
#pragma unroll
            for (int nf = 0; nf < 4; nf++) {
                int col = n0 + wn + nf * 8 + c0;
                if (tA >= 0)
                    redv2(&out[(size_t)tA * HD + col], wA * acc[mi][nf][0], wA * acc[mi][nf][1]);
                if (tB >= 0)
                    redv2(&out[(size_t)tB * HD + col], wB * acc[mi][nf][2], wB * acc[mi][nf][3]);
            }
        }
    }
}

// ---------------- host ----------------
extern "C" void kernel_launch(void* const* d_in, const int* in_sizes, int n_in,
                              void* d_out, int out_size) {
    const float* x  = (const float*)d_in[0];
    const float* gw = (const float*)d_in[1];
    const float* wg = (const float*)d_in[2];
    const float* wu = (const float*)d_in[3];
    const float* wd = (const float*)d_in[4];
    float* out = (float*)d_out;

    float* logits = nullptr;
    if ((long long)out_size >= (long long)TN * HD + (long long)TN * NE)
        logits = out + (size_t)TN * HD;

    void *p_w1, *p_wd, *p_x1, *p_a1;
    cudaGetSymbolAddress(&p_w1, g_w1);
    cudaGetSymbolAddress(&p_wd, g_wd);
    cudaGetSymbolAddress(&p_x1, g_x1);
    cudaGetSymbolAddress(&p_a1, g_a1);

    // Streams/events created ONCE (first call, before the pre-capture baseline).
    static cudaStream_t s1 = nullptr;
    static cudaEvent_t evRoot = nullptr, evC0 = nullptr, evP2 = nullptr;
    if (!s1) {
        cudaStreamCreateWithFlags(&s1, cudaStreamNonBlocking);
        cudaEventCreateWithFlags(&evRoot, cudaEventDisableTiming);
        cudaEventCreateWithFlags(&evC0, cudaEventDisableTiming);
        cudaEventCreateWithFlags(&evP2, cudaEventDisableTiming);
        cudaFuncSetAttribute(k_gemm_fused, cudaFuncAttributeMaxDynamicSharedMemorySize, G_SMEM);
    }

    // default: reset counters FIRST (prep kernels bump queue counters)
    k_zero<<<1, 128>>>();
    cudaEventRecord(evRoot, 0);
    cudaStreamWaitEvent(s1, evRoot, 0);

    // s1: chunk0 gate/up prep (n in [0,2048) -> B' rows [0,4096) = GEMM1 yb<32)
    k_prep0<<<dim3(16, HD/64, NE), 256, PREP_SMEM, s1>>>(wg, (__half*)p_w1, 1);
    k_prep0<<<dim3(16, HD/64, NE), 256, PREP_SMEM, s1>>>(wu, (__half*)p_w1, 2);
    cudaEventRecord(evC0, s1);
    // s1: queue-draining phase-2 prep (chunk1 gate/up + wd), overlaps GEMM1
    k_prep2<<<2048, 256, PREP_SMEM, s1>>>(wg, wu, wd);
    cudaEventRecord(evP2, s1);

    // default: routing chain (k_router also zeroes the output rows)
    k_router<<<TN, 256>>>(x, gw, logits, out);
    k_offsets<<<1, 256>>>();
    k_scatter<<<TN / 256, 256>>>();
    k_gatherx<<<MAXSLOT, 256>>>(x);

    cudaStreamWaitEvent(0, evC0, 0);
    k_gemm_fused<<<dim3(MAXMT, 80), 256, G_SMEM>>>(
        (const __half*)p_x1, (const __half*)p_w1,
        (const __half*)p_a1, (const __half*)p_wd, out, wg, wu, wd);
    // Join s1 back into the capture-origin stream (capture legality). This adds
    // no dependency INTO the fused kernel — k_prep2 overlaps it as intended.
    cudaStreamWaitEvent(0, evP2, 0);
}

// round 17
// speedup vs baseline: 1.1959x; 1.1959x over previous
#include <cuda_runtime.h>
#include <cuda_fp16.h>
#include <math.h>
#include <stdint.h>

// ---------------- problem constants ----------------
#define TN 4096
#define HD 2048
#define ID 4096
#define NE 8
#define NK 2
#define BM 128
#define BN 128
#define BK 64
#define MAXSLOT (TN*NK + NE*BM)   // 9216
#define MAXMT   (MAXSLOT/BM)      // 72
#define STAGE 32768               // A 16K | B 16K
#define G_SMEM (3*STAGE)          // 96 KB -> 2 CTAs/SM

// ---------------- device scratch ----------------
static __device__ __align__(16) __half g_x1 [(size_t)MAXSLOT*HD];      // x fp16
static __device__ __align__(16) __half g_w1 [(size_t)NE*2*ID*HD];      // fine-interleaved gate/up B' fp16
static __device__ __align__(16) __half g_wd [(size_t)NE*HD*ID];        // down W^T fp16
static __device__ __align__(16) __half g_a1 [(size_t)MAXSLOT*ID];      // act fp16
static __device__ int   g_cnt[NE];
static __device__ int   g_cnt2[NE];
static __device__ int   g_off[NE];
static __device__ int   g_tok_e[TN*NK];
static __device__ float g_tok_w[TN*NK];
static __device__ int   g_tok_slot[TN*NK];
static __device__ int   g_slot_token[MAXSLOT];
static __device__ float g_slot_w[MAXSLOT];
static __device__ int   g_tile_e[MAXMT];
static __device__ unsigned int g_done[MAXMT];   // per-mtile GEMM1 completion counters

// ---------------- helpers ----------------
__device__ __forceinline__ uint32_t smem_u32(const void* p) {
    uint32_t a;
    asm("{ .reg .u64 t; cvta.to.shared.u64 t, %1; cvt.u32.u64 %0, t; }" : "=r"(a) : "l"(p));
    return a;
}
__device__ __forceinline__ void cp16(uint32_t dst, const void* src) {
    asm volatile("cp.async.cg.shared.global [%0], [%1], 16;" :: "r"(dst), "l"(src));
}
#define CP_COMMIT() asm volatile("cp.async.commit_group;" ::: "memory")
#define CP_WAIT1()  asm volatile("cp.async.wait_group 1;" ::: "memory")
__device__ __forceinline__ void ldsm4(uint32_t* r, uint32_t addr) {
    asm volatile("ldmatrix.sync.aligned.m8n8.x4.shared.b16 {%0,%1,%2,%3}, [%4];"
        : "=r"(r[0]), "=r"(r[1]), "=r"(r[2]), "=r"(r[3]) : "r"(addr));
}
__device__ __forceinline__ void mmah(float* d, const uint32_t* a, uint32_t b0, uint32_t b1) {
    asm volatile("mma.sync.aligned.m16n8k16.row.col.f32.f16.f16.f32 "
        "{%0,%1,%2,%3}, {%4,%5,%6,%7}, {%8,%9}, {%0,%1,%2,%3};"
        : "+f"(d[0]), "+f"(d[1]), "+f"(d[2]), "+f"(d[3])
        : "r"(a[0]), "r"(a[1]), "r"(a[2]), "r"(a[3]), "r"(b0), "r"(b1));
}
__device__ __forceinline__ void redv2(float* gptr, float a, float b) {
    asm volatile("red.global.add.v2.f32 [%0], {%1, %2};"
        :: "l"(gptr), "f"(a), "f"(b) : "memory");
}
__device__ __forceinline__ unsigned ld_acq(const unsigned* p) {
    unsigned v;
    asm volatile("ld.acquire.gpu.global.u32 %0, [%1];" : "=r"(v) : "l"(p) : "memory");
    return v;
}
__device__ __forceinline__ void red_rel_inc(unsigned* p) {
    asm volatile("red.release.gpu.global.add.u32 [%0], 1;" :: "l"(p) : "memory");
}
__device__ __forceinline__ float gelu_tanh(float v) {
    float w = 0.7978845608028654f * v * (1.0f + 0.044715f * v * v);
    float t;
    asm("tanh.approx.f32 %0, %1;" : "=f"(t) : "f"(w));
    return 0.5f * v * (1.0f + t);
}
__device__ __forceinline__ uint32_t packh2(float a, float b) {
    __half ha = __float2half_rn(a), hb = __float2half_rn(b);
    return (uint32_t)__half_as_ushort(ha) | ((uint32_t)__half_as_ushort(hb) << 16);
}

// ---------------- routing ----------------
__global__ void k_zero() {
    int i = threadIdx.x;
    if (i < NE) { g_cnt[i] = 0; g_cnt2[i] = 0; }
    if (i < MAXMT) g_done[i] = 0;
}

__global__ void k_router(const float* __restrict__ x, const float* __restrict__ gw,
                         float* __restrict__ out_logits, float* __restrict__ out_final) {
    const int t = blockIdx.x;
    const int tid = threadIdx.x;
    // zero this token's output row (GEMM2 accumulates into it)
    {
        float4 z = make_float4(0.f, 0.f, 0.f, 0.f);
        float4* orow = (float4*)(out_final + (size_t)t * HD);
#pragma unroll
        for (int i = 0; i < 2; i++) orow[tid + i * 256] = z;
    }
    float acc[NE];
#pragma unroll
    for (int e = 0; e < NE; e++) acc[e] = 0.f;
    const float* xr = x + (size_t)t * HD;
    for (int h = tid; h < HD; h += 256) {
        float xv = xr[h];
        const float* g = gw + (size_t)h * NE;
#pragma unroll
        for (int e = 0; e < NE; e++) acc[e] += xv * g[e];
    }
    __shared__ float red[256][NE];
#pragma unroll
    for (int e = 0; e < NE; e++) red[tid][e] = acc[e];
    __syncthreads();
    for (int off = 128; off > 0; off >>= 1) {
        if (tid < off) {
#pragma unroll
            for (int e = 0; e < NE; e++) red[tid][e] += red[tid + off][e];
        }
        __syncthreads();
    }
    if (tid == 0) {
        float l[NE];
#pragma unroll
        for (int e = 0; e < NE; e++) l[e] = red[0][e];
        if (out_logits) {
#pragma unroll
            for (int e = 0; e < NE; e++) out_logits[(size_t)t * NE + e] = l[e];
        }
        int e0 = 0;
#pragma unroll
        for (int e = 1; e < NE; e++) if (l[e] > l[e0]) e0 = e;
        int e1 = -1; float l1 = -1e30f;
#pragma unroll
        for (int e = 0; e < NE; e++) if (e != e0 && l[e] > l1) { l1 = l[e]; e1 = e; }
        float d = expf(l1 - l[e0]);
        float w0 = 1.f / (1.f + d);
        g_tok_e[2*t] = e0; g_tok_e[2*t+1] = e1;
        g_tok_w[2*t] = w0; g_tok_w[2*t+1] = 1.f - w0;
        atomicAdd(&g_cnt[e0], 1);
        atomicAdd(&g_cnt[e1], 1);
    }
}

__global__ void k_offsets() {
    const int tid = threadIdx.x;
    if (tid == 0) {
        int cur = 0, mt = 0;
        for (int e = 0; e < NE; e++) {
            g_off[e] = cur;
            int tiles = (g_cnt[e] + BM - 1) / BM;
            for (int j = 0; j < tiles; j++) g_tile_e[mt++] = e;
            cur += tiles * BM;
        }
        for (; mt < MAXMT; mt++) g_tile_e[mt] = -1;
    }
    for (int i = tid; i < MAXSLOT; i += blockDim.x) g_slot_token[i] = -1;
}

__global__ void k_scatter() {
    int t = blockIdx.x * blockDim.x + threadIdx.x;
    if (t >= TN) return;
#pragma unroll
    for (int k = 0; k < NK; k++) {
        int e = g_tok_e[2*t + k];
        int pos = atomicAdd(&g_cnt2[e], 1);
        int slot = g_off[e] + pos;
        g_slot_token[slot] = t;
        g_slot_w[slot] = g_tok_w[2*t + k];
        g_tok_slot[2*t + k] = slot;
    }
}

// ---------------- prep: weight transpose + fp16 convert, coalesced writes ----------------
__global__ void k_prepw(const float* __restrict__ src, __half* __restrict__ dst,
                        int K, int N, int nrows, int mode) {
    __shared__ float s[64 * 129];
    const int e = blockIdx.z;
    const int n0 = blockIdx.x * 128, k0 = blockIdx.y * 64;
    const float* sp = src + (size_t)e * K * N + (size_t)k0 * N + n0;
#pragma unroll
    for (int i = 0; i < 8; i++) {
        int q = threadIdx.x + i * 256;
        int kr = q >> 5, c4 = (q & 31) * 4;
        float4 v = *(const float4*)(sp + (size_t)kr * N + c4);
        float* d = s + kr * 129 + c4;
        d[0] = v.x; d[1] = v.y; d[2] = v.z; d[3] = v.w;
    }
    __syncthreads();
    __half* dp = dst + (size_t)e * nrows * K + k0;
#pragma unroll
    for (int i = 0; i < 4; i++) {
        int j = threadIdx.x + i * 256;
        int n = j >> 3, kq = (j & 7) * 8;
        uint32_t w[4];
#pragma unroll
        for (int t = 0; t < 4; t++)
            w[t] = packh2(s[(kq + 2*t) * 129 + n], s[(kq + 2*t + 1) * 129 + n]);
        int ng = n0 + n;
        size_t row;
        if (mode == 0)      row = (size_t)ng;
        else if (mode == 1) row = (size_t)(ng >> 3) * 16 + (ng & 7);
        else                row = (size_t)(ng >> 3) * 16 + (ng & 7) + 8;
        *(uint4*)(dp + row * K + kq) = *(uint4*)w;
    }
}

// ---------------- prep: gather x rows per slot -> fp16 ----------------
__global__ void k_gatherx(const float* __restrict__ x) {
    int slot = blockIdx.x;
    int t = g_slot_token[slot];
    __half* row = g_x1 + (size_t)slot * HD;
    for (int k = threadIdx.x * 2; k < HD; k += 512) {
        float v0 = 0.f, v1 = 0.f;
        if (t >= 0) {
            v0 = x[(size_t)t * HD + k];
            v1 = x[(size_t)t * HD + k + 1];
        }
        *(uint32_t*)&row[k] = packh2(v0, v1);
    }
}

// ---------------- FUSED GEMM1+GEMM2 in one launch (R14 design) ----------------
// grid (MAXMT, 80): y in [0,64)  -> GEMM1 (x @ B', gelu, write g_a1, release g_done[mt])
//                   y in [64,80) -> GEMM2 (acquire g_done[mt]==64, act @ Wd, red.v2 to out)
// All GEMM1 bids < all GEMM2 bids; monotone dispatch => no deadlock.
__global__ void __launch_bounds__(256, 2)
k_gemm_fused(const __half* __restrict__ A1, const __half* __restrict__ B1,
             const __half* __restrict__ A2, const __half* __restrict__ B2,
             float* __restrict__ out) {
    const int mt = blockIdx.x;
    const int e = g_tile_e[mt];
    if (e < 0) return;                 // pad tile: both phases skip
    const int m0 = mt * BM;
    extern __shared__ char smraw[];
    const uint32_t sbase = smem_u32(smraw);
    const int tid = threadIdx.x, lane = tid & 31, wid = tid >> 5;
    const int wm = (wid >> 2) * 64, wn = (wid & 3) * 32;
    const int prow = tid >> 3, pkc = tid & 7;
    const uint32_t sw = ((uint32_t)(pkc ^ (prow & 7))) << 4;
    const int lrow = lane & 15, lk = lane >> 4;
    const int r0 = lane >> 2, c0 = (lane & 3) * 2;

    float acc[4][4][4];
#pragma unroll
    for (int i = 0; i < 4; i++)
#pragma unroll
        for (int j = 0; j < 4; j++)
#pragma unroll
            for (int q = 0; q < 4; q++) acc[i][j][q] = 0.f;

    if (blockIdx.y < 64) {
        // ================= GEMM1 =================
        const int yb = blockIdx.y;
        const int nb0 = yb * 128;
        const __half* aptr = A1 + (size_t)(m0 + prow) * HD + pkc * 8;
        const __half* bptr = B1 + ((size_t)e * (2 * ID) + nb0 + prow) * HD + pkc * 8;

        auto load_stage = [&](int s, int c) {
            uint32_t d = sbase + s * STAGE;
            const __half* a = aptr + c * BK;
            const __half* b = bptr + c * BK;
#pragma unroll
            for (int t = 0; t < 4; t++) {
                uint32_t dd = d + (prow + 32*t) * 128 + sw;
                cp16(dd,          a + (size_t)(32*t) * HD);
                cp16(dd + 16384,  b + (size_t)(32*t) * HD);
            }
        };
        load_stage(0, 0); CP_COMMIT();
        load_stage(1, 1); CP_COMMIT();

        const int Kc = HD / BK;   // 32
        for (int c = 0; c < Kc; c++) {
            CP_WAIT1();
            __syncthreads();
            if (c + 2 < Kc) load_stage((c + 2) % 3, c + 2);
            CP_COMMIT();
            const uint32_t sa = sbase + (c % 3) * STAGE;
#pragma unroll
            for (int ks = 0; ks < 4; ks++) {
                uint32_t ah[4][4], bf[2][4];
                const int kc = ks * 2 + lk;
#pragma unroll
                for (int mi = 0; mi < 4; mi++) {
                    int row = wm + mi * 16 + lrow;
                    ldsm4(ah[mi], sa + row * 128 + ((kc ^ (row & 7)) << 4));
                }
#pragma unroll
                for (int ng = 0; ng < 2; ng++) {
                    int row = wn + ng * 16 + lrow;
                    ldsm4(bf[ng], sa + 16384 + row * 128 + ((kc ^ (row & 7)) << 4));
                }
#pragma unroll
                for (int mi = 0; mi < 4; mi++)
#pragma unroll
                    for (int nf = 0; nf < 4; nf++) {
                        const int ng = nf >> 1, p = nf & 1;
                        mmah(acc[mi][nf], ah[mi], bf[ng][p], bf[ng][p + 2]);
                    }
            }
        }

        // epilogue: nf pairs (0,1)/(2,3) = gate/up for same output cols
        const int ob = yb * 64 + (wn >> 1);
#pragma unroll
        for (int mi = 0; mi < 4; mi++) {
            int row = m0 + wm + mi * 16 + r0;
#pragma unroll
            for (int g = 0; g < 2; g++) {
                const float* ag = acc[mi][2*g];
                const float* au = acc[mi][2*g + 1];
                int col = ob + g * 8 + c0;
                float a0 = gelu_tanh(ag[0]) * au[0];
                float a1 = gelu_tanh(ag[1]) * au[1];
                float a2 = gelu_tanh(ag[2]) * au[2];
                float a3 = gelu_tanh(ag[3]) * au[3];
                *(uint32_t*)(g_a1 + (size_t)row * ID + col) = packh2(a0, a1);
                *(uint32_t*)(g_a1 + (size_t)(row + 8) * ID + col) = packh2(a2, a3);
            }
        }
        __syncthreads();                       // all stores of this CTA done
        if (tid == 0) red_rel_inc(&g_done[mt]); // release
    } else {
        // ================= GEMM2 =================
        const int n0 = (blockIdx.y - 64) * BN;
        if (tid == 0) {
            while (ld_acq(&g_done[mt]) < 64u) __nanosleep(128);
        }
        __syncthreads();                       // acquire propagated to CTA

        const __half* aptr = A2 + (size_t)(m0 + prow) * ID + pkc * 8;
        const __half* bptr = B2 + ((size_t)e * HD + n0 + prow) * ID + pkc * 8;

        auto load_stage = [&](int s, int c) {
            uint32_t d = sbase + s * STAGE;
            const __half* a = aptr + c * BK;
            const __half* b = bptr + c * BK;
#pragma unroll
            for (int t = 0; t < 4; t++) {
                uint32_t dd = d + (prow + 32*t) * 128 + sw;
                cp16(dd,          a + (size_t)(32*t) * ID);
                cp16(dd + 16384,  b + (size_t)(32*t) * ID);
            }
        };
        load_stage(0, 0); CP_COMMIT();
        load_stage(1, 1); CP_COMMIT();

        const int Kc = ID / BK;   // 64
        for (int c = 0; c < Kc; c++) {
            CP_WAIT1();
            __syncthreads();
            if (c + 2 < Kc) load_stage((c + 2) % 3, c + 2);
            CP_COMMIT();
            const uint32_t sa = sbase + (c % 3) * STAGE;
#pragma unroll
            for (int ks = 0; ks < 4; ks++) {
                uint32_t ah[4][4], bf[2][4];
                const int kc = ks * 2 + lk;
#pragma unroll
                for (int mi = 0; mi < 4; mi++) {
                    int row = wm + mi * 16 + lrow;
                    ldsm4(ah[mi], sa + row * 128 + ((kc ^ (row & 7)) << 4));
                }
#pragma unroll
                for (int ng = 0; ng < 2; ng++) {
                    int row = wn + ng * 16 + lrow;
                    ldsm4(bf[ng], sa + 16384 + row * 128 + ((kc ^ (row & 7)) << 4));
                }
#pragma unroll
                for (int mi = 0; mi < 4; mi++)
#pragma unroll
                    for (int nf = 0; nf < 4; nf++) {
                        const int ng = nf >> 1, p = nf & 1;
                        mmah(acc[mi][nf], ah[mi], bf[ng][p], bf[ng][p + 2]);
                    }
            }
        }

        // fused combine epilogue: out[token, col] += w_slot * acc  (red.v2)
#pragma unroll
        for (int mi = 0; mi < 4; mi++) {
            int rowA = m0 + wm + mi * 16 + r0;
            int rowB = rowA + 8;
            int tA = g_slot_token[rowA], tB = g_slot_token[rowB];
            float wA = g_slot_w[rowA],  wB = g_slot_w[rowB];
#pragma unroll
            for (int nf = 0; nf < 4; nf++) {
                int col = n0 + wn + nf * 8 + c0;
                if (tA >= 0)
                    redv2(&out[(size_t)tA * HD + col], wA * acc[mi][nf][0], wA * acc[mi][nf][1]);
                if (tB >= 0)
                    redv2(&out[(size_t)tB * HD + col], wB * acc[mi][nf][2], wB * acc[mi][nf][3]);
            }
        }
    }
}

// ---------------- host ----------------
extern "C" void kernel_launch(void* const* d_in, const int* in_sizes, int n_in,
                              void* d_out, int out_size) {
    const float* x  = (const float*)d_in[0];
    const float* gw = (const float*)d_in[1];
    const float* wg = (const float*)d_in[2];
    const float* wu = (const float*)d_in[3];
    const float* wd = (const float*)d_in[4];
    float* out = (float*)d_out;

    float* logits = nullptr;
    if ((long long)out_size >= (long long)TN * HD + (long long)TN * NE)
        logits = out + (size_t)TN * HD;

    void *p_w1, *p_wd, *p_x1, *p_a1;
    cudaGetSymbolAddress(&p_w1, g_w1);
    cudaGetSymbolAddress(&p_wd, g_wd);
    cudaGetSymbolAddress(&p_x1, g_x1);
    cudaGetSymbolAddress(&p_a1, g_a1);

    // Streams/events created ONCE (first call, before the pre-capture baseline)
    // and reused forever — no allocation during/after graph capture.
    static cudaStream_t s1 = nullptr, s2 = nullptr, s3 = nullptr;
    static cudaEvent_t evRoot = nullptr, ev1 = nullptr, ev2 = nullptr, ev3 = nullptr;
    if (!s1) {
        cudaStreamCreateWithFlags(&s1, cudaStreamNonBlocking);
        cudaStreamCreateWithFlags(&s2, cudaStreamNonBlocking);
        cudaStreamCreateWithFlags(&s3, cudaStreamNonBlocking);
        cudaEventCreateWithFlags(&evRoot, cudaEventDisableTiming);
        cudaEventCreateWithFlags(&ev1, cudaEventDisableTiming);
        cudaEventCreateWithFlags(&ev2, cudaEventDisableTiming);
        cudaEventCreateWithFlags(&ev3, cudaEventDisableTiming);
        cudaFuncSetAttribute(k_gemm_fused, cudaFuncAttributeMaxDynamicSharedMemorySize, G_SMEM);
    }

    cudaEventRecord(evRoot, 0);
    cudaStreamWaitEvent(s1, evRoot, 0);
    cudaStreamWaitEvent(s2, evRoot, 0);
    cudaStreamWaitEvent(s3, evRoot, 0);

    // Concurrent weight prep: gate/s1, up/s2, wd/s3 (higher aggregate DRAM BW)
    k_prepw<<<dim3(ID/128, HD/64, NE), 256, 0, s1>>>(wg, (__half*)p_w1, HD, ID, 2*ID, 1);
    cudaEventRecord(ev1, s1);
    k_prepw<<<dim3(ID/128, HD/64, NE), 256, 0, s2>>>(wu, (__half*)p_w1, HD, ID, 2*ID, 2);
    cudaEventRecord(ev2, s2);
    k_prepw<<<dim3(HD/128, ID/64, NE), 256, 0, s3>>>(wd, (__half*)p_wd, ID, HD, HD, 0);
    cudaEventRecord(ev3, s3);

    // default: routing chain (k_router also zeroes the output rows)
    k_zero<<<1, 128>>>();
    k_router<<<TN, 256>>>(x, gw, logits, out);
    k_offsets<<<1, 256>>>();
    k_scatter<<<TN / 256, 256>>>();
    k_gatherx<<<MAXSLOT, 256>>>(x);

    cudaStreamWaitEvent(0, ev1, 0);
    cudaStreamWaitEvent(0, ev2, 0);
    cudaStreamWaitEvent(0, ev3, 0);
    k_gemm_fused<<<dim3(MAXMT, 80), 256, G_SMEM>>>(
        (const __half*)p_x1, (const __half*)p_w1,
        (const __half*)p_a1, (const __half*)p_wd, out);
}